// round 1
// baseline (speedup 1.0000x reference)
#include <cuda_runtime.h>
#include <math.h>

// Problem dims (fixed by setup_inputs)
#define Bsz 512
#define Dsz 128
#define Isz 64
#define Hd  256      // decoder hidden
#define HeN 512      // encoder hidden
#define KeN (Isz + HeN)   // 576 combined K for encoder step

// ---------------- device scratch (static, no allocations) ----------------
__device__ float g_h_e[2][Bsz * HeN];          // ping-pong encoder h
__device__ float g_c_e[Bsz * HeN];             // encoder c
__device__ float g_c_d[Bsz * Hd];              // decoder c (init = z)
__device__ float g_hs[Dsz][Bsz * Hd];          // decoder h sequence, [t][b*Hd+u] (64 MB)

__device__ __forceinline__ float sigm(float x) { return 1.0f / (1.0f + expf(-x)); }

// ---------------- init: zero encoder state ----------------
__global__ void init_kernel() {
    int i = blockIdx.x * blockDim.x + threadIdx.x;
    if (i < Bsz * HeN) {
        g_h_e[0][i] = 0.0f;
        g_c_e[i]    = 0.0f;
    }
}

// ---------------- small outputs: mu_c copy, softplus, softmax(8) ----------------
__global__ void small_kernel(const float* __restrict__ mu_c_raw,
                             const float* __restrict__ sig_lat,
                             const float* __restrict__ phi_lat,
                             float* __restrict__ out_muc,
                             float* __restrict__ out_sig,
                             float* __restrict__ out_phi) {
    int tid = threadIdx.x;
    for (int i = tid; i < 8 * Hd; i += blockDim.x) {
        out_muc[i] = mu_c_raw[i];
        float v = sig_lat[i];
        out_sig[i] = fmaxf(v, 0.0f) + log1pf(expf(-fabsf(v)));
    }
    if (tid == 0) {
        float m = -1e30f;
        for (int i = 0; i < 8; ++i) m = fmaxf(m, phi_lat[i]);
        float e[8]; float s = 0.0f;
        for (int i = 0; i < 8; ++i) { e[i] = expf(phi_lat[i] - m); s += e[i]; }
        float inv = 1.0f / s;
        for (int i = 0; i < 8; ++i) out_phi[i] = e[i] * inv;
    }
}

// ---------------- encoder step: fused [512,576]@[576,2048] GEMM + peephole gates ----
// block tile: 64 batch rows x 32 hidden units (x4 gates). grid (8,16), 256 threads.
// thread: 8 rows x 1 unit x 4 gates. A reads broadcast, W reads conflict-free.
__global__ __launch_bounds__(256) void enc_step_kernel(
    const float* __restrict__ X, const float* __restrict__ Wm,
    const float* __restrict__ A,
    const float* __restrict__ Wx, const float* __restrict__ Wh,
    const float* __restrict__ bias,
    const float* __restrict__ wci, const float* __restrict__ wcf,
    const float* __restrict__ wco, int t) {
    __shared__ float As[32][65];    // [kk][m], padded vs STS bank conflicts
    __shared__ float Ws[32][128];   // [kk][g*32+u]

    const float* __restrict__ h_in  = g_h_e[t & 1];
    float* __restrict__       h_out = g_h_e[(t + 1) & 1];

    const int bm0 = blockIdx.x * 64;
    const int bu0 = blockIdx.y * 32;
    const int tid = threadIdx.x;
    const int tx  = tid & 31;       // unit within tile
    const int ty  = tid >> 5;       // row group (8 rows each)
    const int uu  = bu0 + tx;

    float acc[8][4];
#pragma unroll
    for (int g = 0; g < 4; ++g) {
        float bb = bias[g * HeN + uu];
#pragma unroll
        for (int r = 0; r < 8; ++r) acc[r][g] = bb;
    }

    for (int kc = 0; kc < KeN; kc += 32) {
        // A tile: 64 rows x 32 k  (x-projection for k<64, recurrent h for k>=64)
#pragma unroll
        for (int i = 0; i < 8; ++i) {
            int idx = tid + i * 256;
            int m   = idx >> 5;
            int kk  = idx & 31;
            int k   = kc + kk;
            int row = bm0 + m;
            float v;
            if (k < Isz) {
                int gi = (row * Dsz + t) * Isz + k;
                float w = Wm[gi];
                v = X[gi] * w + A[t * Isz + k] * (1.0f - w);
            } else {
                v = h_in[row * HeN + (k - Isz)];
            }
            As[kk][m] = v;
        }
        // W tile: 32 k x (4 gates x 32 units)
#pragma unroll
        for (int i = 0; i < 16; ++i) {
            int idx = tid + i * 256;
            int u   = idx & 31;
            int g   = (idx >> 5) & 3;
            int kk  = idx >> 7;
            int k   = kc + kk;
            int col = g * HeN + bu0 + u;
            float v = (k < Isz) ? Wx[k * (4 * HeN) + col]
                                : Wh[(k - Isz) * (4 * HeN) + col];
            Ws[kk][g * 32 + u] = v;
        }
        __syncthreads();
#pragma unroll
        for (int kk = 0; kk < 32; ++kk) {
            float a[8];
#pragma unroll
            for (int r = 0; r < 8; ++r) a[r] = As[kk][ty * 8 + r];
            float w0 = Ws[kk][tx];
            float w1 = Ws[kk][32 + tx];
            float w2 = Ws[kk][64 + tx];
            float w3 = Ws[kk][96 + tx];
#pragma unroll
            for (int r = 0; r < 8; ++r) {
                acc[r][0] += a[r] * w0;
                acc[r][1] += a[r] * w1;
                acc[r][2] += a[r] * w2;
                acc[r][3] += a[r] * w3;
            }
        }
        __syncthreads();
    }

    const float ci = wci[uu], cf = wcf[uu], co = wco[uu];
#pragma unroll
    for (int r = 0; r < 8; ++r) {
        int row = bm0 + ty * 8 + r;
        int cix = row * HeN + uu;
        float c_old = g_c_e[cix];
        float ig = sigm(acc[r][0] + c_old * ci);
        float fg = sigm(acc[r][1] + c_old * cf);
        float cn = fg * c_old + ig * tanhf(acc[r][2]);
        float og = sigm(acc[r][3] + cn * co);
        g_c_e[cix] = cn;
        h_out[cix] = og * tanhf(cn);
    }
}

// ---------------- latent z + small latent outputs + decoder c0 ----------------
__global__ void z_kernel(const float* __restrict__ noise,
                         float* __restrict__ out_z,
                         float* __restrict__ out_mu,
                         float* __restrict__ out_ls) {
    int idx = blockIdx.x * blockDim.x + threadIdx.x;
    if (idx >= Bsz * Hd) return;
    int b = idx >> 8;         // /256
    int u = idx & 255;
    const float* hT = g_h_e[0];     // after 128 steps, final h lives in buffer 0
    float mu = hT[b * HeN + u];
    float ls = hT[b * HeN + Hd + u];
    float zz = mu + expf(0.5f * ls) * noise[idx];
    out_mu[idx] = mu;
    out_ls[idx] = ls;
    out_z[idx]  = zz;
    g_c_d[idx]  = zz;               // decoder c0 = z
}

// ---------------- decoder step: [512,256]@[256,1024] + gates (inputs are zero) ----
// block tile: 32 rows x 32 units. grid (16,8), 256 threads; thread: 4 rows x 1 unit x 4 gates.
__global__ __launch_bounds__(256) void dec_step_kernel(
    const float* __restrict__ Wh,
    const float* __restrict__ bias,
    const float* __restrict__ wci, const float* __restrict__ wcf,
    const float* __restrict__ wco, int t) {
    __shared__ float As[32][33];
    __shared__ float Ws[32][128];

    const int bm0 = blockIdx.x * 32;
    const int bu0 = blockIdx.y * 32;
    const int tid = threadIdx.x;
    const int tx  = tid & 31;
    const int ty  = tid >> 5;   // 0..7, 4 rows each
    const int uu  = bu0 + tx;

    float acc[4][4];
#pragma unroll
    for (int g = 0; g < 4; ++g) {
        float bb = bias[g * Hd + uu];
#pragma unroll
        for (int r = 0; r < 4; ++r) acc[r][g] = bb;
    }

    if (t > 0) {
        const float* __restrict__ h_in = g_hs[t - 1];
        for (int kc = 0; kc < Hd; kc += 32) {
#pragma unroll
            for (int i = 0; i < 4; ++i) {
                int idx = tid + i * 256;
                int m = idx >> 5, kk = idx & 31;
                As[kk][m] = h_in[(bm0 + m) * Hd + kc + kk];
            }
#pragma unroll
            for (int i = 0; i < 16; ++i) {
                int idx = tid + i * 256;
                int u = idx & 31, g = (idx >> 5) & 3, kk = idx >> 7;
                Ws[kk][g * 32 + u] = Wh[(kc + kk) * (4 * Hd) + g * Hd + bu0 + u];
            }
            __syncthreads();
#pragma unroll
            for (int kk = 0; kk < 32; ++kk) {
                float a[4];
#pragma unroll
                for (int r = 0; r < 4; ++r) a[r] = As[kk][ty * 4 + r];
                float w0 = Ws[kk][tx];
                float w1 = Ws[kk][32 + tx];
                float w2 = Ws[kk][64 + tx];
                float w3 = Ws[kk][96 + tx];
#pragma unroll
                for (int r = 0; r < 4; ++r) {
                    acc[r][0] += a[r] * w0;
                    acc[r][1] += a[r] * w1;
                    acc[r][2] += a[r] * w2;
                    acc[r][3] += a[r] * w3;
                }
            }
            __syncthreads();
        }
    }

    const float ci = wci[uu], cf = wcf[uu], co = wco[uu];
#pragma unroll
    for (int r = 0; r < 4; ++r) {
        int row = bm0 + ty * 4 + r;
        int cix = row * Hd + uu;
        float c_old = g_c_d[cix];
        float ig = sigm(acc[r][0] + c_old * ci);
        float fg = sigm(acc[r][1] + c_old * cf);
        float cn = fg * c_old + ig * tanhf(acc[r][2]);
        float og = sigm(acc[r][3] + cn * co);
        g_c_d[cix]   = cn;
        g_hs[t][cix] = og * tanhf(cn);
    }
}

// ---------------- output projection: hs @ Wout + bout, sigmoid ----------------
// grid (128 t, 32 b-chunks of 16), 256 threads. thread: 4 rows x 1 col.
__global__ __launch_bounds__(256) void out_kernel(
    const float* __restrict__ Wout, const float* __restrict__ bout,
    float* __restrict__ out_x, float* __restrict__ out_xraw) {
    __shared__ float Hs[16][256];
    const int t  = blockIdx.x;
    const int b0 = blockIdx.y * 16;
    const int tid = threadIdx.x;

    const float* __restrict__ hrow = g_hs[t];
#pragma unroll
    for (int i = 0; i < 16; ++i) {
        int idx = tid + i * 256;
        int r = idx >> 8, k = idx & 255;
        Hs[r][k] = hrow[(b0 + r) * Hd + k];
    }
    __syncthreads();

    const int c  = tid & 63;
    const int rg = tid >> 6;    // 0..3
    float acc[4] = {0.f, 0.f, 0.f, 0.f};
    for (int k = 0; k < 256; ++k) {
        float w = Wout[k * Isz + c];
#pragma unroll
        for (int j = 0; j < 4; ++j) acc[j] += Hs[rg * 4 + j][k] * w;
    }
    float bo = bout[c];
#pragma unroll
    for (int j = 0; j < 4; ++j) {
        int row = b0 + rg * 4 + j;       // batch index
        float xr = acc[j] + bo;
        int oi = (row * Dsz + t) * Isz + c;
        out_xraw[oi] = xr;
        out_x[oi]    = 1.0f / (1.0f + expf(-xr));
    }
}

// ---------------- launch ----------------
extern "C" void kernel_launch(void* const* d_in, const int* in_sizes, int n_in,
                              void* d_out, int out_size) {
    (void)in_sizes; (void)n_in; (void)out_size;
    const float* X      = (const float*)d_in[0];
    const float* Wm     = (const float*)d_in[1];
    const float* noise  = (const float*)d_in[2];
    const float* A      = (const float*)d_in[3];
    const float* Wx_e   = (const float*)d_in[4];
    const float* Wh_e   = (const float*)d_in[5];
    const float* b_e    = (const float*)d_in[6];
    const float* wci_e  = (const float*)d_in[7];
    const float* wcf_e  = (const float*)d_in[8];
    const float* wco_e  = (const float*)d_in[9];
    // d_in[10] = Wx_d : unused (decoder inputs are zero)
    const float* Wh_d   = (const float*)d_in[11];
    const float* b_d    = (const float*)d_in[12];
    const float* wci_d  = (const float*)d_in[13];
    const float* wcf_d  = (const float*)d_in[14];
    const float* wco_d  = (const float*)d_in[15];
    const float* Wout   = (const float*)d_in[16];
    const float* bout   = (const float*)d_in[17];
    const float* mu_c_r = (const float*)d_in[18];
    const float* sig_l  = (const float*)d_in[19];
    const float* phi_l  = (const float*)d_in[20];

    float* out = (float*)d_out;
    // concatenation of (x, x_raw, mu_c, sigma2_c, phi_c, z, mu_tilde, log_sigma2_tilde)
    float* out_x    = out;                 // 4194304
    float* out_xraw = out + 4194304;       // 4194304
    float* out_muc  = out + 8388608;       // 2048
    float* out_sig  = out + 8390656;       // 2048
    float* out_phi  = out + 8392704;       // 8
    float* out_z    = out + 8392712;       // 131072
    float* out_mu   = out + 8523784;       // 131072
    float* out_ls   = out + 8654856;       // 131072

    init_kernel<<<(Bsz * HeN + 255) / 256, 256>>>();
    small_kernel<<<1, 256>>>(mu_c_r, sig_l, phi_l, out_muc, out_sig, out_phi);

    for (int t = 0; t < Dsz; ++t) {
        enc_step_kernel<<<dim3(Bsz / 64, HeN / 32), 256>>>(
            X, Wm, A, Wx_e, Wh_e, b_e, wci_e, wcf_e, wco_e, t);
    }

    z_kernel<<<(Bsz * Hd + 255) / 256, 256>>>(noise, out_z, out_mu, out_ls);

    for (int t = 0; t < Dsz; ++t) {
        dec_step_kernel<<<dim3(Bsz / 32, Hd / 32), 256>>>(
            Wh_d, b_d, wci_d, wcf_d, wco_d, t);
    }

    out_kernel<<<dim3(Dsz, Bsz / 16), 256>>>(Wout, bout, out_x, out_xraw);
}